// round 6
// baseline (speedup 1.0000x reference)
#include <cuda_runtime.h>
#include <math.h>
#include <stdint.h>

// ---------------- problem constants ----------------
#define Bb      2
#define Ll      4096
#define DMODEL  1024
#define DINNER  2048
#define NHEADS  32
#define HEADDIM 64
#define DSTATE  128
#define DCONV   4
#define DIP     4384      // 2*DINNER + 2*DSTATE + NHEADS
#define CONVDIM 2304      // DINNER + 2*DSTATE
#define BL      (Bb*Ll)   // 8192
#define DOUT    1024
#define NQ      4         // DSTATE split factor in the scan

// ---------------- device scratch (no allocations allowed) ----------------
__device__ float g_zx [(size_t)BL * DIP];       // in_proj output
__device__ float g_xbc[(size_t)BL * CONVDIM];   // conv+silu out
__device__ float g_y  [(size_t)BL * DINNER];    // normed out (tf32 bits) -> GEMM2
__device__ float g_yp [(size_t)NQ * BL * DINNER]; // scan partial sums (per n-quarter)
__device__ float g_dt [BL * NHEADS];
__device__ float g_dA [BL * NHEADS];
__device__ float g_xc [(size_t)BL * DMODEL];    // x, tf32-rounded
__device__ float g_w1 [(size_t)DIP * DMODEL];   // in_proj_w, tf32-rounded
__device__ float g_w2 [(size_t)DOUT * DINNER];  // out_proj_w, tf32-rounded

__device__ __forceinline__ uint32_t f2tf(float f) {
    uint32_t r;
    asm("cvt.rna.tf32.f32 %0, %1;" : "=r"(r) : "f"(f));
    return r;
}

// =====================================================================
// Elementwise fp32 -> tf32(RNA)-rounded fp32 bits
// =====================================================================
__global__ __launch_bounds__(256) void cvt_tf32_kernel(
    const float* __restrict__ src, float* __restrict__ dst, int n4)
{
    const int i = blockIdx.x * blockDim.x + threadIdx.x;
    if (i >= n4) return;
    float4 v = ((const float4*)src)[i];
    uint4 u;
    u.x = f2tf(v.x); u.y = f2tf(v.y); u.z = f2tf(v.z); u.w = f2tf(v.w);
    ((uint4*)dst)[i] = u;
}

// =====================================================================
// TF32 tensor-core GEMM (NT), cp.async pipelined (unchanged from R4).
// =====================================================================
#define GSTR 36
#define STAGE_F (128 * GSTR)
#define STAGE_B (2 * STAGE_F * 4)

__device__ __forceinline__ void mma_tf32(float c[4], const uint32_t a[4], const uint32_t b[2]) {
    asm volatile(
        "mma.sync.aligned.m16n8k8.row.col.f32.tf32.tf32.f32 "
        "{%0,%1,%2,%3}, {%4,%5,%6,%7}, {%8,%9}, {%0,%1,%2,%3};"
        : "+f"(c[0]), "+f"(c[1]), "+f"(c[2]), "+f"(c[3])
        : "r"(a[0]), "r"(a[1]), "r"(a[2]), "r"(a[3]), "r"(b[0]), "r"(b[1]));
}

__global__ __launch_bounds__(256, 2) void gemm_tf32_ca_kernel(
    const float* __restrict__ A, const float* __restrict__ Bw,
    float* __restrict__ C, int M, int N, int K)
{
    extern __shared__ float sm[];

    const int tid  = threadIdx.x;
    const int lane = tid & 31;
    const int warp = tid >> 5;
    const int wm = (warp >> 2) * 64;
    const int wn = (warp & 3) * 32;
    const int bm = blockIdx.y * 128;
    const int bn = blockIdx.x * 128;

    const int crow = tid >> 1;
    const int ccol = (tid & 1) * 16;
    const float* Ag = A  + (size_t)(bm + crow) * K + ccol;
    const float* Bg = Bw + (size_t)(bn + crow) * K + ccol;
    const int bsz = ((bn + crow) < N) ? 16 : 0;
    const uint32_t sbase = (uint32_t)__cvta_generic_to_shared(sm)
                         + (uint32_t)(crow * GSTR + ccol) * 4u;

#define G_ISSUE(kt, s) do {                                                   \
        const float* ag_ = Ag + (size_t)(kt) * 32;                            \
        const float* bg_ = Bg + (size_t)(kt) * 32;                            \
        uint32_t da_ = sbase + (s) * STAGE_B;                                 \
        uint32_t db_ = da_ + STAGE_F * 4;                                     \
        _Pragma("unroll")                                                     \
        for (int i_ = 0; i_ < 4; i_++)                                        \
            asm volatile("cp.async.cg.shared.global [%0], [%1], 16;"          \
                         :: "r"(da_ + i_ * 16), "l"(ag_ + i_ * 4));           \
        _Pragma("unroll")                                                     \
        for (int i_ = 0; i_ < 4; i_++)                                        \
            asm volatile("cp.async.cg.shared.global [%0], [%1], 16, %2;"      \
                         :: "r"(db_ + i_ * 16), "l"(bg_ + i_ * 4), "r"(bsz)); \
        asm volatile("cp.async.commit_group;");                               \
    } while (0)

    float acc[4][4][4];
#pragma unroll
    for (int mt = 0; mt < 4; mt++)
#pragma unroll
        for (int nt = 0; nt < 4; nt++)
#pragma unroll
            for (int i = 0; i < 4; i++) acc[mt][nt][i] = 0.f;

    const int KT = K / 32;
    G_ISSUE(0, 0);
    G_ISSUE(1, 1);

    for (int kt = 0; kt < KT; kt++) {
        asm volatile("cp.async.wait_group 1;");
        __syncthreads();

        const float* As = sm + (kt & 1) * (2 * STAGE_F);
        const float* Bs = As + STAGE_F;

#pragma unroll
        for (int ks = 0; ks < 4; ks++) {
            const int k = ks * 8 + (lane & 3);
            uint32_t af[4][4];
#pragma unroll
            for (int mt = 0; mt < 4; mt++) {
                const int m = wm + mt * 16 + (lane >> 2);
                af[mt][0] = __float_as_uint(As[m       * GSTR + k]);
                af[mt][1] = __float_as_uint(As[(m + 8) * GSTR + k]);
                af[mt][2] = __float_as_uint(As[m       * GSTR + k + 4]);
                af[mt][3] = __float_as_uint(As[(m + 8) * GSTR + k + 4]);
            }
            uint32_t bf[4][2];
#pragma unroll
            for (int nt = 0; nt < 4; nt++) {
                const int n = wn + nt * 8 + (lane >> 2);
                bf[nt][0] = __float_as_uint(Bs[n * GSTR + k]);
                bf[nt][1] = __float_as_uint(Bs[n * GSTR + k + 4]);
            }
#pragma unroll
            for (int mt = 0; mt < 4; mt++)
#pragma unroll
                for (int nt = 0; nt < 4; nt++)
                    mma_tf32(acc[mt][nt], af[mt], bf[nt]);
        }

        __syncthreads();
        if (kt + 2 < KT) G_ISSUE(kt + 2, kt & 1);
    }

#pragma unroll
    for (int mt = 0; mt < 4; mt++) {
        const int row = bm + wm + mt * 16 + (lane >> 2);
#pragma unroll
        for (int nt = 0; nt < 4; nt++) {
            const int col = bn + wn + nt * 8 + (lane & 3) * 2;
            if (col < N) {
                *(float2*)&C[(size_t)row * N + col]       = make_float2(acc[mt][nt][0], acc[mt][nt][1]);
                *(float2*)&C[(size_t)(row + 8) * N + col] = make_float2(acc[mt][nt][2], acc[mt][nt][3]);
            }
        }
    }
#undef G_ISSUE
}

// =====================================================================
// Depthwise causal conv (taps=4) + bias + SiLU
// =====================================================================
__global__ __launch_bounds__(256) void conv_silu_kernel(
    const float* __restrict__ conv_w, const float* __restrict__ conv_b)
{
    const int idx = blockIdx.x * blockDim.x + threadIdx.x;
    const int total = BL * CONVDIM;
    if (idx >= total) return;
    const int c  = idx % CONVDIM;
    const int bl = idx / CONVDIM;
    const int l  = bl & (Ll - 1);

    float acc = conv_b[c];
    const float* col = g_zx + (size_t)bl * DIP + DINNER + c;
#pragma unroll
    for (int j = 0; j < 4; j++) {
        const int ls = l - 3 + j;
        if (ls >= 0)
            acc = fmaf(col[(long)(j - 3) * DIP], conv_w[c * 4 + j], acc);
    }
    g_xbc[idx] = acc / (1.f + expf(-acc));
}

// =====================================================================
// dt: softplus(dt_raw + bias); dA = exp(dt * (-exp(A_log)))
// =====================================================================
__global__ __launch_bounds__(256) void dt_kernel(
    const float* __restrict__ dt_bias, const float* __restrict__ A_log)
{
    const int idx = blockIdx.x * blockDim.x + threadIdx.x;
    if (idx >= BL * NHEADS) return;
    const int h  = idx & (NHEADS - 1);
    const int bl = idx >> 5;
    float raw = g_zx[(size_t)bl * DIP + DINNER + CONVDIM + h] + dt_bias[h];
    float dt = (raw > 20.f) ? raw : log1pf(expf(raw));
    float A = -expf(A_log[h]);
    g_dt[idx] = dt;
    g_dA[idx] = expf(dt * A);
}

// =====================================================================
// Selective scan, state-split x4, shuffle-free.
// Block = (b, h, phalf, nquarter): 512 blocks, 256 threads.
// Thread (p = tid>>3 in [0,32), ns = tid&7) holds 4 states of its
// 32-state quarter. Per-step partials -> smem; one cooperative
// reduction per 8-step chunk (256 thr = 8d x 32p). Partial y per
// quarter goes to g_yp[nq]; gatenorm sums the quarters.
// =====================================================================
#define DCH 8

__global__ __launch_bounds__(256) void scan_kernel(const float* __restrict__ Dp)
{
    const int bx = blockIdx.x;
    const int nq = bx & 3;
    const int ph = (bx >> 2) & 1;
    const int h  = (bx >> 3) & 31;
    const int b  = bx >> 8;
    const int tid = threadIdx.x;
    const int p  = tid >> 3;     // 0..31
    const int ns = tid & 7;      // 0..7

    __shared__ float s_bc[2][DCH][64];     // [0:32)=B quarter, [32:64)=C quarter
    __shared__ float s_x [2][DCH][32];
    __shared__ float s_dt[2][DCH];
    __shared__ float s_dA[2][DCH];
    __shared__ float s_part[DCH][32][9];   // per-step partial sums

    float hs[4] = {0.f, 0.f, 0.f, 0.f};

    const float* base = g_xbc + (size_t)b * Ll * CONVDIM;
    const float* dtp  = g_dt  + (size_t)b * Ll * NHEADS + h;
    const float* dAp  = g_dA  + (size_t)b * Ll * NHEADS + h;
    const float Dh = Dp[h];
    const int xoff = h * 64 + ph * 32;

    // staging indices: bc -> thread covers (d0, c) and (d0+4, c)
    const int c  = tid & 63;
    const int d0 = tid >> 6;                      // 0..3
    const int gcol = DINNER + nq * 32 + (c < 32 ? c : DSTATE + c - 32);
    const int dx = tid >> 5;                      // 0..7 (x staging)
    const int px = tid & 31;

    // reduction indices: thread -> (dr, pr)
    const int dr = tid >> 5;                      // 0..7
    const int pr = tid & 31;                      // 0..31

    // ---- prologue: chunk 0 straight to smem ----
    s_bc[0][d0    ][c] = base[(size_t)d0       * CONVDIM + gcol];
    s_bc[0][d0 + 4][c] = base[(size_t)(d0 + 4) * CONVDIM + gcol];
    s_x[0][dx][px]     = base[(size_t)dx * CONVDIM + xoff + px];
    if (tid < DCH)          s_dt[0][tid]     = dtp[(size_t)tid * NHEADS];
    else if (tid < 2 * DCH) s_dA[0][tid - 8] = dAp[(size_t)(tid - 8) * NHEADS];

    // ---- prefetch chunk 1 into registers ----
    float pf0 = base[(size_t)(DCH + d0    ) * CONVDIM + gcol];
    float pf1 = base[(size_t)(DCH + d0 + 4) * CONVDIM + gcol];
    float pfx = base[(size_t)(DCH + dx) * CONVDIM + xoff + px];
    float pfdt = 0.f, pfdA = 0.f;
    if (tid < DCH)          pfdt = dtp[(size_t)(DCH + tid) * NHEADS];
    else if (tid < 2 * DCH) pfdA = dAp[(size_t)(DCH + tid - 8) * NHEADS];
    __syncthreads();

    float* yq = g_yp + (size_t)nq * BL * DINNER + (size_t)b * Ll * DINNER + xoff + pr;

    const int NCH = Ll / DCH;
    int buf = 0;
    for (int ci = 0; ci < NCH; ci++) {
        // 1) publish chunk ci+1 into the idle buffer
        if (ci + 1 < NCH) {
            s_bc[buf ^ 1][d0    ][c] = pf0;
            s_bc[buf ^ 1][d0 + 4][c] = pf1;
            s_x[buf ^ 1][dx][px]     = pfx;
            if (tid < DCH)          s_dt[buf ^ 1][tid]     = pfdt;
            else if (tid < 2 * DCH) s_dA[buf ^ 1][tid - 8] = pfdA;
        }
        // 2) issue loads for chunk ci+2
        if (ci + 2 < NCH) {
            const size_t t2 = (size_t)(ci + 2) * DCH;
            pf0 = base[(t2 + d0    ) * CONVDIM + gcol];
            pf1 = base[(t2 + d0 + 4) * CONVDIM + gcol];
            pfx = base[(t2 + dx) * CONVDIM + xoff + px];
            if (tid < DCH)          pfdt = dtp[(t2 + tid) * NHEADS];
            else if (tid < 2 * DCH) pfdA = dAp[(t2 + tid - 8) * NHEADS];
        }
        // 3) 8 scan steps from the current buffer
#pragma unroll
        for (int d = 0; d < DCH; d++) {
            const float cdt = s_dt[buf][d];
            const float cdA = s_dA[buf][d];
            const float kx  = cdt * s_x[buf][d][p];
            const float4 Bv = *(const float4*)&s_bc[buf][d][ns * 4];
            const float4 Cv = *(const float4*)&s_bc[buf][d][32 + ns * 4];
            float a0, a1;
            hs[0] = fmaf(hs[0], cdA, kx * Bv.x); a0 = hs[0] * Cv.x;
            hs[1] = fmaf(hs[1], cdA, kx * Bv.y); a0 = fmaf(hs[1], Cv.y, a0);
            hs[2] = fmaf(hs[2], cdA, kx * Bv.z); a1 = hs[2] * Cv.z;
            hs[3] = fmaf(hs[3], cdA, kx * Bv.w); a1 = fmaf(hs[3], Cv.w, a1);
            s_part[d][p][ns] = a0 + a1;
        }
        __syncthreads();   // s_part + published buffer complete

        // 4) cooperative reduction: thread (dr, pr) sums 8 partials
        {
            const float* sp = s_part[dr][pr];
            float sum = ((sp[0] + sp[1]) + (sp[2] + sp[3]))
                      + ((sp[4] + sp[5]) + (sp[6] + sp[7]));
            if (nq == 0) sum = fmaf(Dh, s_x[buf][dr][pr], sum);
            yq[(size_t)(ci * DCH + dr) * DINNER] = sum;
        }
        __syncthreads();   // protect s_part / s_x before next chunk
        buf ^= 1;
    }
}

// =====================================================================
// y = (sum of 4 scan partials) * silu(z); RMSnorm; store tf32-rounded
// =====================================================================
__global__ __launch_bounds__(256) void gatenorm_kernel(const float* __restrict__ norm_w)
{
    const int row = blockIdx.x;
    const float* zrow = g_zx + (size_t)row * DIP;
    const float* y0 = g_yp + (size_t)row * DINNER;
    const float* y1 = y0 + (size_t)BL * DINNER;
    const float* y2 = y1 + (size_t)BL * DINNER;
    const float* y3 = y2 + (size_t)BL * DINNER;
    float* yrow = g_y + (size_t)row * DINNER;

    float v[8];
    float ss = 0.f;
#pragma unroll
    for (int i = 0; i < 8; i++) {
        const int c = threadIdx.x + i * 256;
        float d = (y0[c] + y1[c]) + (y2[c] + y3[c]);
        float z = zrow[c];
        float g = d * (z / (1.f + expf(-z)));
        v[i] = g;
        ss = fmaf(g, g, ss);
    }
#pragma unroll
    for (int o = 16; o; o >>= 1) ss += __shfl_xor_sync(0xffffffffu, ss, o);

    __shared__ float red[8];
    if ((threadIdx.x & 31) == 0) red[threadIdx.x >> 5] = ss;
    __syncthreads();
    float tot = 0.f;
#pragma unroll
    for (int w = 0; w < 8; w++) tot += red[w];
    const float scale = rsqrtf(tot * (1.f / (float)DINNER) + 1e-5f);

#pragma unroll
    for (int i = 0; i < 8; i++) {
        const int c = threadIdx.x + i * 256;
        yrow[c] = __uint_as_float(f2tf(v[i] * scale * norm_w[c]));
    }
}

// =====================================================================
// launch
// =====================================================================
extern "C" void kernel_launch(void* const* d_in, const int* in_sizes, int n_in,
                              void* d_out, int out_size)
{
    const float* x          = (const float*)d_in[0];
    const float* in_proj_w  = (const float*)d_in[1];
    const float* conv_w     = (const float*)d_in[2];
    const float* conv_b     = (const float*)d_in[3];
    const float* dt_bias    = (const float*)d_in[4];
    const float* A_log      = (const float*)d_in[5];
    const float* Dp         = (const float*)d_in[6];
    const float* norm_w     = (const float*)d_in[7];
    const float* out_proj_w = (const float*)d_in[8];
    float* out = (float*)d_out;

    float *zx, *yb, *xc, *w1, *w2;
    cudaGetSymbolAddress((void**)&zx, g_zx);
    cudaGetSymbolAddress((void**)&yb, g_y);
    cudaGetSymbolAddress((void**)&xc, g_xc);
    cudaGetSymbolAddress((void**)&w1, g_w1);
    cudaGetSymbolAddress((void**)&w2, g_w2);

    cudaFuncSetAttribute(gemm_tf32_ca_kernel,
                         cudaFuncAttributeMaxDynamicSharedMemorySize, 2 * STAGE_B);

    // 0) pre-round GEMM inputs to tf32 (RNA)
    {
        int n4;
        n4 = (BL * DMODEL) / 4;
        cvt_tf32_kernel<<<(n4 + 255) / 256, 256>>>(x, xc, n4);
        n4 = (DIP * DMODEL) / 4;
        cvt_tf32_kernel<<<(n4 + 255) / 256, 256>>>(in_proj_w, w1, n4);
        n4 = (DOUT * DINNER) / 4;
        cvt_tf32_kernel<<<(n4 + 255) / 256, 256>>>(out_proj_w, w2, n4);
    }
    // 1) in_proj GEMM
    {
        dim3 grid((DIP + 127) / 128, BL / 128);
        gemm_tf32_ca_kernel<<<grid, 256, 2 * STAGE_B>>>(xc, w1, zx, BL, DIP, DMODEL);
    }
    // 2) depthwise conv + silu
    {
        const int total = BL * CONVDIM;
        conv_silu_kernel<<<(total + 255) / 256, 256>>>(conv_w, conv_b);
    }
    // 3) dt softplus + dA
    dt_kernel<<<(BL * NHEADS) / 256, 256>>>(dt_bias, A_log);
    // 4) state-split scan (512 blocks)
    scan_kernel<<<NQ * 2 * Bb * NHEADS, 256>>>(Dp);
    // 5) gate + RMSnorm (sums 4 partials, writes tf32-rounded)
    gatenorm_kernel<<<BL, 256>>>(norm_w);
    // 6) out_proj GEMM
    {
        dim3 grid(DOUT / 128, BL / 128);
        gemm_tf32_ca_kernel<<<grid, 256, 2 * STAGE_B>>>(yb, w2, out, BL, DOUT, DINNER);
    }
}

// round 7
// speedup vs baseline: 1.1714x; 1.1714x over previous
#include <cuda_runtime.h>
#include <math.h>
#include <stdint.h>

#define Bb      2
#define Ll      4096
#define DMODEL  1024
#define DINNER  2048
#define NHEADS  32
#define HEADDIM 64
#define DSTATE  128
#define DIP     4384
#define CONVDIM 2304
#define BL      (Bb*Ll)
#define DOUT    1024
#define Q       32
#define NC      (Ll/Q)
#define SSTATE  (HEADDIM*DSTATE)
#define BSTR    132
#define XSTR    36

__device__ float g_zx   [(size_t)BL * DIP];
__device__ float g_xbc  [(size_t)BL * CONVDIM];
__device__ float g_y    [(size_t)BL * DINNER];
__device__ float g_dt   [BL * NHEADS];
__device__ float g_dA   [BL * NHEADS];          // a = dt*A (log decay)
__device__ float g_xc   [(size_t)BL * DMODEL];
__device__ float g_w1   [(size_t)DIP * DMODEL];
__device__ float g_w2   [(size_t)DOUT * DINNER];
__device__ float g_state[(size_t)Bb*NHEADS * NC * SSTATE];
__device__ float g_sprev[(size_t)Bb*NHEADS * NC * SSTATE];
__device__ float g_ca   [(size_t)Bb*NHEADS * NC * Q];

__device__ __forceinline__ uint32_t f2tf(float f) {
    uint32_t r; asm("cvt.rna.tf32.f32 %0, %1;" : "=r"(r) : "f"(f)); return r;
}
__device__ __forceinline__ void split_store(float v, float* hi, float* lo) {
    float h = __uint_as_float(f2tf(v));
    *hi = h; *lo = __uint_as_float(f2tf(v - h));
}
__device__ __forceinline__ void mma_tf32(float c[4], const uint32_t a[4], const uint32_t b[2]) {
    asm volatile(
        "mma.sync.aligned.m16n8k8.row.col.f32.tf32.tf32.f32 "
        "{%0,%1,%2,%3}, {%4,%5,%6,%7}, {%8,%9}, {%0,%1,%2,%3};"
        : "+f"(c[0]), "+f"(c[1]), "+f"(c[2]), "+f"(c[3])
        : "r"(a[0]), "r"(a[1]), "r"(a[2]), "r"(a[3]), "r"(b[0]), "r"(b[1]));
}
__device__ __forceinline__ void mma_split(float c[4], const uint32_t ah[4], const uint32_t al[4],
                                          const uint32_t bh[2], const uint32_t bl[2]) {
    mma_tf32(c, ah, bh); mma_tf32(c, ah, bl); mma_tf32(c, al, bh);
}

__global__ __launch_bounds__(256) void cvt_tf32_kernel(
    const float* __restrict__ src, float* __restrict__ dst, int n4)
{
    const int i = blockIdx.x * blockDim.x + threadIdx.x;
    if (i >= n4) return;
    float4 v = ((const float4*)src)[i];
    uint4 u;
    u.x = f2tf(v.x); u.y = f2tf(v.y); u.z = f2tf(v.z); u.w = f2tf(v.w);
    ((uint4*)dst)[i] = u;
}

// ============== TF32 GEMM (NT), cp.async pipelined (unchanged) ==============
#define GSTR 36
#define STAGE_F (128 * GSTR)
#define STAGE_B (2 * STAGE_F * 4)

__global__ __launch_bounds__(256, 2) void gemm_tf32_ca_kernel(
    const float* __restrict__ A, const float* __restrict__ Bw,
    float* __restrict__ C, int M, int N, int K)
{
    extern __shared__ float sm[];
    const int tid  = threadIdx.x;
    const int lane = tid & 31;
    const int warp = tid >> 5;
    const int wm = (warp >> 2) * 64;
    const int wn = (warp & 3) * 32;
    const int bm = blockIdx.y * 128;
    const int bn = blockIdx.x * 128;

    const int crow = tid >> 1;
    const int ccol = (tid & 1) * 16;
    const float* Ag = A  + (size_t)(bm + crow) * K + ccol;
    const float* Bg = Bw + (size_t)(bn + crow) * K + ccol;
    const int bsz = ((bn + crow) < N) ? 16 : 0;
    const uint32_t sbase = (uint32_t)__cvta_generic_to_shared(sm)
                         + (uint32_t)(crow * GSTR + ccol) * 4u;

#define G_ISSUE(kt, s) do {                                                   \
        const float* ag_ = Ag + (size_t)(kt) * 32;                            \
        const float* bg_ = Bg + (size_t)(kt) * 32;                            \
        uint32_t da_ = sbase + (s) * STAGE_B;                                 \
        uint32_t db_ = da_ + STAGE_F * 4;                                     \
        _Pragma("unroll")                                                     \
        for (int i_ = 0; i_ < 4; i_++)                                        \
            asm volatile("cp.async.cg.shared.global [%0], [%1], 16;"          \
                         :: "r"(da_ + i_ * 16), "l"(ag_ + i_ * 4));           \
        _Pragma("unroll")                                                     \
        for (int i_ = 0; i_ < 4; i_++)                                        \
            asm volatile("cp.async.cg.shared.global [%0], [%1], 16, %2;"      \
                         :: "r"(db_ + i_ * 16), "l"(bg_ + i_ * 4), "r"(bsz)); \
        asm volatile("cp.async.commit_group;");                               \
    } while (0)

    float acc[4][4][4];
#pragma unroll
    for (int mt = 0; mt < 4; mt++)
#pragma unroll
        for (int nt = 0; nt < 4; nt++)
#pragma unroll
            for (int i = 0; i < 4; i++) acc[mt][nt][i] = 0.f;

    const int KT = K / 32;
    G_ISSUE(0, 0);
    G_ISSUE(1, 1);

    for (int kt = 0; kt < KT; kt++) {
        asm volatile("cp.async.wait_group 1;");
        __syncthreads();
        const float* As = sm + (kt & 1) * (2 * STAGE_F);
        const float* Bs = As + STAGE_F;
#pragma unroll
        for (int ks = 0; ks < 4; ks++) {
            const int k = ks * 8 + (lane & 3);
            uint32_t af[4][4];
#pragma unroll
            for (int mt = 0; mt < 4; mt++) {
                const int m = wm + mt * 16 + (lane >> 2);
                af[mt][0] = __float_as_uint(As[m       * GSTR + k]);
                af[mt][1] = __float_as_uint(As[(m + 8) * GSTR + k]);
                af[mt][2] = __float_as_uint(As[m       * GSTR + k + 4]);
                af[mt][3] = __float_as_uint(As[(m + 8) * GSTR + k + 4]);
            }
            uint32_t bf[4][2];
#pragma unroll
            for (int nt = 0; nt < 4; nt++) {
                const int n = wn + nt * 8 + (lane >> 2);
                bf[nt][0] = __float_as_uint(Bs[n * GSTR + k]);
                bf[nt][1] = __float_as_uint(Bs[n * GSTR + k + 4]);
            }
#pragma unroll
            for (int mt = 0; mt < 4; mt++)
#pragma unroll
                for (int nt = 0; nt < 4; nt++)
                    mma_tf32(acc[mt][nt], af[mt], bf[nt]);
        }
        __syncthreads();
        if (kt + 2 < KT) G_ISSUE(kt + 2, kt & 1);
    }

#pragma unroll
    for (int mt = 0; mt < 4; mt++) {
        const int row = bm + wm + mt * 16 + (lane >> 2);
#pragma unroll
        for (int nt = 0; nt < 4; nt++) {
            const int col = bn + wn + nt * 8 + (lane & 3) * 2;
            if (col < N) {
                *(float2*)&C[(size_t)row * N + col]       = make_float2(acc[mt][nt][0], acc[mt][nt][1]);
                *(float2*)&C[(size_t)(row + 8) * N + col] = make_float2(acc[mt][nt][2], acc[mt][nt][3]);
            }
        }
    }
#undef G_ISSUE
}

// ============== depthwise conv + SiLU ==============
__global__ __launch_bounds__(256) void conv_silu_kernel(
    const float* __restrict__ conv_w, const float* __restrict__ conv_b)
{
    const int idx = blockIdx.x * blockDim.x + threadIdx.x;
    if (idx >= BL * CONVDIM) return;
    const int c  = idx % CONVDIM;
    const int bl = idx / CONVDIM;
    const int l  = bl & (Ll - 1);
    float acc = conv_b[c];
    const float* col = g_zx + (size_t)bl * DIP + DINNER + c;
#pragma unroll
    for (int j = 0; j < 4; j++) {
        const int ls = l - 3 + j;
        if (ls >= 0) acc = fmaf(col[(long)(j - 3) * DIP], conv_w[c * 4 + j], acc);
    }
    g_xbc[idx] = acc / (1.f + expf(-acc));
}

// ============== dt: softplus; a = dt * (-exp(A_log)) ==============
__global__ __launch_bounds__(256) void dt_kernel(
    const float* __restrict__ dt_bias, const float* __restrict__ A_log)
{
    const int idx = blockIdx.x * blockDim.x + threadIdx.x;
    if (idx >= BL * NHEADS) return;
    const int h  = idx & (NHEADS - 1);
    const int bl = idx >> 5;
    float raw = g_zx[(size_t)bl * DIP + DINNER + CONVDIM + h] + dt_bias[h];
    float dt = (raw > 20.f) ? raw : log1pf(expf(raw));
    float A = -expf(A_log[h]);
    g_dt[idx] = dt;
    g_dA[idx] = dt * A;
}

// ============== SSD K1: chunk-local Y_intra, state S_c, cumsum ca ==============
__global__ __launch_bounds__(256, 2) void ssd_chunk_kernel()
{
    extern __shared__ float smf[];
    float* sBhi = smf;
    float* sBlo = sBhi + Q * BSTR;
    float* sWhi = sBlo + Q * BSTR;   // C, later Bw
    float* sWlo = sWhi + Q * BSTR;
    float* sXhi = sWlo + Q * BSTR;   // Xt [64][XSTR]
    float* sXlo = sXhi + 64 * XSTR;
    float* sMhi = sXlo + 64 * XSTR;  // [Q][XSTR]
    float* sMlo = sMhi + Q * XSTR;
    float* s_dt = sMlo + Q * XSTR;
    float* s_ca = s_dt + Q;
    float* s_w  = s_ca + Q;

    const int tid  = threadIdx.x;
    const int lane = tid & 31;
    const int warp = tid >> 5;
    const int bx = blockIdx.x;
    const int h = bx & 31;
    const int c = (bx >> 5) & (NC - 1);
    const int b = bx >> 12;
    const int t0 = c * Q;
    const int bh = b * NHEADS + h;
    const float* xbase = g_xbc + ((size_t)b * Ll + t0) * CONVDIM;

    { // stage B, C (split) and Xt (split, transposed)
        const int t   = tid >> 3;
        const int seg = (tid & 7) * 16;
        const float4* srcB = (const float4*)(xbase + (size_t)t * CONVDIM + DINNER + seg);
        const float4* srcC = (const float4*)(xbase + (size_t)t * CONVDIM + DINNER + DSTATE + seg);
#pragma unroll
        for (int j = 0; j < 4; j++) {
            float4 vb = srcB[j], vc = srcC[j];
            const int n = seg + j * 4;
            split_store(vb.x, &sBhi[t*BSTR+n+0], &sBlo[t*BSTR+n+0]);
            split_store(vb.y, &sBhi[t*BSTR+n+1], &sBlo[t*BSTR+n+1]);
            split_store(vb.z, &sBhi[t*BSTR+n+2], &sBlo[t*BSTR+n+2]);
            split_store(vb.w, &sBhi[t*BSTR+n+3], &sBlo[t*BSTR+n+3]);
            split_store(vc.x, &sWhi[t*BSTR+n+0], &sWlo[t*BSTR+n+0]);
            split_store(vc.y, &sWhi[t*BSTR+n+1], &sWlo[t*BSTR+n+1]);
            split_store(vc.z, &sWhi[t*BSTR+n+2], &sWlo[t*BSTR+n+2]);
            split_store(vc.w, &sWhi[t*BSTR+n+3], &sWlo[t*BSTR+n+3]);
        }
        const int px = (tid & 7) * 8;
        const float4* srcX = (const float4*)(xbase + (size_t)t * CONVDIM + h * 64 + px);
#pragma unroll
        for (int j = 0; j < 2; j++) {
            float4 v = srcX[j];
            const int p = px + j * 4;
            split_store(v.x, &sXhi[(p+0)*XSTR+t], &sXlo[(p+0)*XSTR+t]);
            split_store(v.y, &sXhi[(p+1)*XSTR+t], &sXlo[(p+1)*XSTR+t]);
            split_store(v.z, &sXhi[(p+2)*XSTR+t], &sXlo[(p+2)*XSTR+t]);
            split_store(v.w, &sXhi[(p+3)*XSTR+t], &sXlo[(p+3)*XSTR+t]);
        }
    }
    if (tid < 32) { // dt, inclusive cumsum(a), end-weight w
        const size_t rb = ((size_t)b * Ll + t0 + tid) * NHEADS + h;
        const float dtv = g_dt[rb];
        float cum = g_dA[rb];
        s_dt[tid] = dtv;
#pragma unroll
        for (int o = 1; o < 32; o <<= 1) {
            float nb = __shfl_up_sync(0xffffffffu, cum, o);
            if (tid >= o) cum += nb;
        }
        s_ca[tid] = cum;
        g_ca[((size_t)bh * NC + c) * Q + tid] = cum;
        const float tot = __shfl_sync(0xffffffffu, cum, 31);
        s_w[tid] = dtv * expf(tot - cum);
    }
    __syncthreads();

    // G = C @ B^T (32x32x128), warp grid 2x4 (m16 x n8)
    const int wmG = (warp >> 2) * 16;
    const int wnG = (warp & 3) * 8;
    float gacc[4] = {0.f, 0.f, 0.f, 0.f};
#pragma unroll
    for (int ks = 0; ks < 16; ks++) {
        const int k = ks * 8 + (lane & 3);
        const int m = wmG + (lane >> 2);
        uint32_t ah[4], al[4];
        ah[0] = __float_as_uint(sWhi[m*BSTR+k]);     al[0] = __float_as_uint(sWlo[m*BSTR+k]);
        ah[1] = __float_as_uint(sWhi[(m+8)*BSTR+k]); al[1] = __float_as_uint(sWlo[(m+8)*BSTR+k]);
        ah[2] = __float_as_uint(sWhi[m*BSTR+k+4]);   al[2] = __float_as_uint(sWlo[m*BSTR+k+4]);
        ah[3] = __float_as_uint(sWhi[(m+8)*BSTR+k+4]);al[3] = __float_as_uint(sWlo[(m+8)*BSTR+k+4]);
        const int n = wnG + (lane >> 2);
        uint32_t bh2[2], bl2[2];
        bh2[0] = __float_as_uint(sBhi[n*BSTR+k]);    bl2[0] = __float_as_uint(sBlo[n*BSTR+k]);
        bh2[1] = __float_as_uint(sBhi[n*BSTR+k+4]);  bl2[1] = __float_as_uint(sBlo[n*BSTR+k+4]);
        mma_split(gacc, ah, al, bh2, bl2);
    }
    __syncthreads();

    { // build M (masked, decayed); overwrite W buffer with Bw = B * w_t
#pragma unroll
        for (int i = 0; i < 4; i++) {
            const int t = wmG + (lane >> 2) + (i >> 1) * 8;
            const int s = wnG + (lane & 3) * 2 + (i & 1);
            float v = 0.f;
            if (s <= t) v = gacc[i] * s_dt[s] * expf(s_ca[t] - s_ca[s]);
            split_store(v, &sMhi[t*XSTR+s], &sMlo[t*XSTR+s]);
        }
        const int tB = tid >> 3;
        const int n0 = (tid & 7) * 16;
        const float w = s_w[tB];
#pragma unroll
        for (int i = 0; i < 16; i++) {
            const int n = n0 + i;
            float v = (sBhi[tB*BSTR+n] + sBlo[tB*BSTR+n]) * w;
            split_store(v, &sWhi[tB*BSTR+n], &sWlo[tB*BSTR+n]);
        }
    }
    __syncthreads();

    { // Y_intra = M @ X (32x64x32), warp grid 2x4 (m16 x n16)
        const int wm = (warp >> 2) * 16;
        const int wp = (warp & 3) * 16;
        float yacc[2][4];
#pragma unroll
        for (int nt = 0; nt < 2; nt++)
#pragma unroll
            for (int i = 0; i < 4; i++) yacc[nt][i] = 0.f;
#pragma unroll
        for (int ks = 0; ks < 4; ks++) {
            const int k = ks * 8 + (lane & 3);
            const int m = wm + (lane >> 2);
            uint32_t ah[4], al[4];
            ah[0] = __float_as_uint(sMhi[m*XSTR+k]);      al[0] = __float_as_uint(sMlo[m*XSTR+k]);
            ah[1] = __float_as_uint(sMhi[(m+8)*XSTR+k]);  al[1] = __float_as_uint(sMlo[(m+8)*XSTR+k]);
            ah[2] = __float_as_uint(sMhi[m*XSTR+k+4]);    al[2] = __float_as_uint(sMlo[m*XSTR+k+4]);
            ah[3] = __float_as_uint(sMhi[(m+8)*XSTR+k+4]);al[3] = __float_as_uint(sMlo[(m+8)*XSTR+k+4]);
#pragma unroll
            for (int nt = 0; nt < 2; nt++) {
                const int p = wp + nt * 8 + (lane >> 2);
                uint32_t bh2[2], bl2[2];
                bh2[0] = __float_as_uint(sXhi[p*XSTR+k]);   bl2[0] = __float_as_uint(sXlo[p*XSTR+k]);
                bh2[1] = __float_as_uint(sXhi[p*XSTR+k+4]); bl2[1] = __float_as_uint(sXlo[p*XSTR+k+4]);
                mma_split(yacc[nt], ah, al, bh2, bl2);
            }
        }
        float* yout = g_y + ((size_t)b * Ll + t0) * DINNER + h * 64;
#pragma unroll
        for (int nt = 0; nt < 2; nt++) {
            const int t = wm + (lane >> 2);
            const int p = wp + nt * 8 + (lane & 3) * 2;
            *(float2*)&yout[(size_t)t * DINNER + p]       = make_float2(yacc[nt][0], yacc[nt][1]);
            *(float2*)&yout[(size_t)(t + 8) * DINNER + p] = make_float2(yacc[nt][2], yacc[nt][3]);
        }
    }

    { // S_c = Xt @ Bw^T (64x128x32), warp grid 4x2 (m16 x n64)
        const int wp = (warp >> 1) * 16;
        const int wn = (warp & 1) * 64;
        float sacc[8][4];
#pragma unroll
        for (int nt = 0; nt < 8; nt++)
#pragma unroll
            for (int i = 0; i < 4; i++) sacc[nt][i] = 0.f;
#pragma unroll
        for (int ks = 0; ks < 4; ks++) {
            const int k = ks * 8 + (lane & 3);
            const int m = wp + (lane >> 2);
            uint32_t ah[4], al[4];
            ah[0] = __float_as_uint(sXhi[m*XSTR+k]);      al[0] = __float_as_uint(sXlo[m*XSTR+k]);
            ah[1] = __float_as_uint(sXhi[(m+8)*XSTR+k]);  al[1] = __float_as_uint(sXlo[(m+8)*XSTR+k]);
            ah[2] = __float_as_uint(sXhi[m*XSTR+k+4]);    al[2] = __float_as_uint(sXlo[m*XSTR+k+4]);
            ah[3] = __float_as_uint(sXhi[(m+8)*XSTR+k+4]);al[3] = __float_as_uint(sXlo[(m+8)*XSTR+k+4]);
#pragma unroll
            for (int nt = 0; nt < 8; nt++) {
                const int n = wn + nt * 8 + (lane >> 2);
                uint32_t bh2[2], bl2[2];
                bh2[0] = __float_as_uint(sWhi[k*BSTR+n]);     bl2[0] = __float_as_uint(sWlo[k*BSTR+n]);
                bh2[1] = __float_as_uint(sWhi[(k+4)*BSTR+n]); bl2[1] = __float_as_uint(sWlo[(k+4)*BSTR+n]);
                mma_split(sacc[nt], ah, al, bh2, bl2);
            }
        }
        float* sout = g_state + ((size_t)bh * NC + c) * SSTATE;
#pragma unroll
        for (int nt = 0; nt < 8; nt++) {
            const int p = wp + (lane >> 2);
            const int n = wn + nt * 8 + (lane & 3) * 2;
            *(float2*)&sout[(size_t)p * DSTATE + n]       = make_float2(sacc[nt][0], sacc[nt][1]);
            *(float2*)&sout[(size_t)(p + 8) * DSTATE + n] = make_float2(sacc[nt][2], sacc[nt][3]);
        }
    }
}

// ============== SSD K2: inter-chunk exclusive state scan ==============
__global__ __launch_bounds__(256) void ssd_state_scan_kernel()
{
    const int bh = blockIdx.x >> 4;
    const int sl = blockIdx.x & 15;
    const int off = sl * 512 + threadIdx.x * 2;
    const size_t base = (size_t)bh * NC * SSTATE + off;
    const float* ca = g_ca + (size_t)bh * NC * Q + (Q - 1);

    float2 run = make_float2(0.f, 0.f);
#pragma unroll 4
    for (int c = 0; c < NC; c++) {
        *(float2*)&g_sprev[base + (size_t)c * SSTATE] = run;
        const float P = expf(ca[(size_t)c * Q]);
        const float2 v = *(const float2*)&g_state[base + (size_t)c * SSTATE];
        run.x = fmaf(run.x, P, v.x);
        run.y = fmaf(run.y, P, v.y);
    }
}

// ============== SSD K3: y += exp(ca)*C@S_prev^T + D*x ==============
__global__ __launch_bounds__(256, 2) void ssd_inter_kernel(const float* __restrict__ Dp)
{
    extern __shared__ float smf[];
    float* sChi = smf;
    float* sClo = sChi + Q * BSTR;
    float* sShi = sClo + Q * BSTR;
    float* sSlo = sShi + 64 * BSTR;
    float* s_ca = sSlo + 64 * BSTR;

    const int tid  = threadIdx.x;
    const int lane = tid & 31;
    const int warp = tid >> 5;
    const int bx = blockIdx.x;
    const int h = bx & 31;
    const int c = (bx >> 5) & (NC - 1);
    const int b = bx >> 12;
    const int t0 = c * Q;
    const int bh = b * NHEADS + h;
    const float* xbase = g_xbc + ((size_t)b * Ll + t0) * CONVDIM;

    {
        const int t   = tid >> 3;
        const int seg = (tid & 7) * 16;
        const float4* srcC = (const float4*)(xbase + (size_t)t * CONVDIM + DINNER + DSTATE + seg);
#pragma unroll
        for (int j = 0; j < 4; j++) {
            float4 v = srcC[j];
            const int n = seg + j * 4;
            split_store(v.x, &sChi[t*BSTR+n+0], &sClo[t*BSTR+n+0]);
            split_store(v.y, &sChi[t*BSTR+n+1], &sClo[t*BSTR+n+1]);
            split_store(v.z, &sChi[t*BSTR+n+2], &sClo[t*BSTR+n+2]);
            split_store(v.w, &sChi[t*BSTR+n+3], &sClo[t*BSTR+n+3]);
        }
        const int p   = tid >> 2;
        const int nsg = (tid & 3) * 32;
        const float4* srcS = (const float4*)(g_sprev + ((size_t)bh * NC + c) * SSTATE
                                             + (size_t)p * DSTATE + nsg);
#pragma unroll
        for (int j = 0; j < 8; j++) {
            float4 v = srcS[j];
            const int n = nsg + j * 4;
            split_store(v.x, &sShi[p*BSTR+n+0], &sSlo[p*BSTR+n+0]);
            split_store(v.y, &sShi[p*BSTR+n+1], &sSlo[p*BSTR+n+1]);
            split_store(v.z, &sShi[p*BSTR+n+2], &sSlo[p*BSTR+n+2]);
            split_store(v.w, &sShi[p*BSTR+n+3], &sSlo[p*BSTR+n+3]);
        }
        if (tid < 32) s_ca[tid] = g_ca[((size_t)bh * NC + c) * Q + tid];
    }
    __syncthreads();

    const int wm = (warp >> 2) * 16;
    const int wp = (warp & 3) * 16;
    float acc[2][4];
#pragma unroll
    for (int nt = 0; nt < 2; nt++)
#pragma unroll
        for (int i = 0; i < 4; i++) acc[nt][i] = 0.f;

#pragma unroll
    for (int ks = 0; ks < 16; ks++) {
        const int k = ks * 8 + (lane & 3);
        const int m = wm + (lane >> 2);
        uint32_t ah[4], al[4];
        ah[0] = __float_as_uint(sChi[m*BSTR+k]);      al[0] = __float_as_uint(sClo[m*BSTR+k]);
        ah[1] = __float_as_uint(sChi[(m+8)*BSTR+k]);  al[1] = __float_as_uint(sClo[(m+8)*BSTR+k]);
        ah[2] = __float_as_uint(sChi[m*BSTR+k+4]);    al[2] = __float_as_uint(sClo[m*BSTR+k+4]);
        ah[3] = __float_as_uint(sChi[(m+8)*BSTR+k+4]);al[3] = __float_as_uint(sClo[(m+8)*BSTR+k+4]);
#pragma unroll
        for (int nt = 0; nt < 2; nt++) {
            const int p = wp + nt * 8 + (lane >> 2);
            uint32_t bh2[2], bl2[2];
            bh2[0] = __float_as_uint(sShi[p*BSTR+k]);   bl2[0] = __float_as_uint(sSlo[p*BSTR+k]);
            bh2[1] = __float_as_uint(sShi[p*BSTR+k+4]); bl2[1] = __float_as_uint(sSlo[p*BSTR+k+4]);
            mma_split(acc[nt], ah, al, bh2, bl2);
        }
    }

    const float Dh = Dp[h];
    float* yout = g_y + ((size_t)b * Ll + t0) * DINNER + h * 64;
    const float* xsrc = xbase + h * 64;
#pragma unroll
    for (int nt = 0; nt < 2; nt++) {
#pragma unroll
        for (int half = 0; half < 2; half++) {
            const int t = wm + (lane >> 2) + half * 8;
            const int p = wp + nt * 8 + (lane & 3) * 2;
            const float e = expf(s_ca[t]);
            float2 xv = *(const float2*)(xsrc + (size_t)t * CONVDIM + p);
            float2 yo = *(float2*)(yout + (size_t)t * DINNER + p);
            yo.x += e * acc[nt][half * 2 + 0] + Dh * xv.x;
            yo.y += e * acc[nt][half * 2 + 1] + Dh * xv.y;
            *(float2*)(yout + (size_t)t * DINNER + p) = yo;
        }
    }
}

// ============== gate + RMSnorm (tf32-rounded out) ==============
__global__ __launch_bounds__(256) void gatenorm_kernel(const float* __restrict__ norm_w)
{
    const int row = blockIdx.x;
    const float* zrow = g_zx + (size_t)row * DIP;
    float* yrow = g_y + (size_t)row * DINNER;

    float v[8];
    float ss = 0.f;
#pragma unroll
    for (int i = 0; i < 8; i++) {
        const int c = threadIdx.x + i * 256;
        float d = yrow[c];
        float z = zrow[c];
        float g = d * (z / (1.f + expf(-z)));
        v[i] = g;
        ss = fmaf(g, g, ss);
    }
#pragma unroll
    for (int o = 16; o; o >>= 1) ss += __shfl_xor_sync(0xffffffffu, ss, o);

    __shared__ float red[8];
    if ((threadIdx.x & 31) == 0) red[threadIdx.x >> 5] = ss;
    __syncthreads();
    float tot = 0.f;
#pragma unroll
    for (int w = 0; w < 8; w++) tot += red[w];
    const float scale = rsqrtf(tot * (1.f / (float)DINNER) + 1e-5f);

#pragma unroll
    for (int i = 0; i < 8; i++) {
        const int c = threadIdx.x + i * 256;
        yrow[c] = __uint_as_float(f2tf(v[i] * scale * norm_w[c]));
    }
}

// ============== launch ==============
extern "C" void kernel_launch(void* const* d_in, const int* in_sizes, int n_in,
                              void* d_out, int out_size)
{
    const float* x          = (const float*)d_in[0];
    const float* in_proj_w  = (const float*)d_in[1];
    const float* conv_w     = (const float*)d_in[2];
    const float* conv_b     = (const float*)d_in[3];
    const float* dt_bias    = (const float*)d_in[4];
    const float* A_log      = (const float*)d_in[5];
    const float* Dp         = (const float*)d_in[6];
    const float* norm_w     = (const float*)d_in[7];
    const float* out_proj_w = (const float*)d_in[8];
    float* out = (float*)d_out;

    float *zx, *yb, *xc, *w1, *w2;
    cudaGetSymbolAddress((void**)&zx, g_zx);
    cudaGetSymbolAddress((void**)&yb, g_y);
    cudaGetSymbolAddress((void**)&xc, g_xc);
    cudaGetSymbolAddress((void**)&w1, g_w1);
    cudaGetSymbolAddress((void**)&w2, g_w2);

    const int k1_smem = (4 * Q * BSTR + 2 * 64 * XSTR + 2 * Q * XSTR + 3 * Q) * 4;
    const int k3_smem = (2 * Q * BSTR + 2 * 64 * BSTR + Q) * 4;
    cudaFuncSetAttribute(gemm_tf32_ca_kernel,
                         cudaFuncAttributeMaxDynamicSharedMemorySize, 2 * STAGE_B);
    cudaFuncSetAttribute(ssd_chunk_kernel,
                         cudaFuncAttributeMaxDynamicSharedMemorySize, k1_smem);
    cudaFuncSetAttribute(ssd_inter_kernel,
                         cudaFuncAttributeMaxDynamicSharedMemorySize, k3_smem);

    {
        int n4;
        n4 = (BL * DMODEL) / 4;
        cvt_tf32_kernel<<<(n4 + 255) / 256, 256>>>(x, xc, n4);
        n4 = (DIP * DMODEL) / 4;
        cvt_tf32_kernel<<<(n4 + 255) / 256, 256>>>(in_proj_w, w1, n4);
        n4 = (DOUT * DINNER) / 4;
        cvt_tf32_kernel<<<(n4 + 255) / 256, 256>>>(out_proj_w, w2, n4);
    }
    {
        dim3 grid((DIP + 127) / 128, BL / 128);
        gemm_tf32_ca_kernel<<<grid, 256, 2 * STAGE_B>>>(xc, w1, zx, BL, DIP, DMODEL);
    }
    {
        const int total = BL * CONVDIM;
        conv_silu_kernel<<<(total + 255) / 256, 256>>>(conv_w, conv_b);
    }
    dt_kernel<<<(BL * NHEADS) / 256, 256>>>(dt_bias, A_log);
    ssd_chunk_kernel<<<Bb * NC * NHEADS, 256, k1_smem>>>();
    ssd_state_scan_kernel<<<Bb * NHEADS * 16, 256>>>();
    ssd_inter_kernel<<<Bb * NC * NHEADS, 256, k3_smem>>>(Dp);
    gatenorm_kernel<<<BL, 256>>>(norm_w);
    {
        dim3 grid(DOUT / 128, BL / 128);
        gemm_tf32_ca_kernel<<<grid, 256, 2 * STAGE_B>>>(yb, w2, out, BL, DOUT, DINNER);
    }
}

// round 9
// speedup vs baseline: 1.2749x; 1.0884x over previous
#include <cuda_runtime.h>
#include <math.h>
#include <stdint.h>

#define Bb      2
#define Ll      4096
#define DMODEL  1024
#define DINNER  2048
#define NHEADS  32
#define HEADDIM 64
#define DSTATE  128
#define DIP     4384
#define CONVDIM 2304
#define BL      (Bb*Ll)
#define DOUT    1024
#define Q       32
#define NC      (Ll/Q)
#define SSTATE  (HEADDIM*DSTATE)
#define BSTR    132
#define XSTR    36

__device__ float g_zx   [(size_t)BL * DIP];
__device__ float g_xbc  [(size_t)BL * CONVDIM];
__device__ float g_y    [(size_t)BL * DINNER];
__device__ float g_dt   [BL * NHEADS];
__device__ float g_dA   [BL * NHEADS];          // a = dt*A (log decay)
__device__ float g_xc   [(size_t)BL * DMODEL];
__device__ float g_w1   [(size_t)DIP * DMODEL];
__device__ float g_w2   [(size_t)DOUT * DINNER];
__device__ float g_state[(size_t)Bb*NHEADS * NC * SSTATE];
__device__ float g_sprev[(size_t)Bb*NHEADS * NC * SSTATE];
__device__ float g_ca   [(size_t)Bb*NHEADS * NC * Q];

__device__ __forceinline__ uint32_t f2tf(float f) {
    uint32_t r; asm("cvt.rna.tf32.f32 %0, %1;" : "=r"(r) : "f"(f)); return r;
}
__device__ __forceinline__ void split_store(float v, float* hi, float* lo) {
    float h = __uint_as_float(f2tf(v));
    *hi = h; *lo = __uint_as_float(f2tf(v - h));
}
__device__ __forceinline__ void mma_tf32(float c[4], const uint32_t a[4], const uint32_t b[2]) {
    asm volatile(
        "mma.sync.aligned.m16n8k8.row.col.f32.tf32.tf32.f32 "
        "{%0,%1,%2,%3}, {%4,%5,%6,%7}, {%8,%9}, {%0,%1,%2,%3};"
        : "+f"(c[0]), "+f"(c[1]), "+f"(c[2]), "+f"(c[3])
        : "r"(a[0]), "r"(a[1]), "r"(a[2]), "r"(a[3]), "r"(b[0]), "r"(b[1]));
}
__device__ __forceinline__ void mma_split(float c[4], const uint32_t ah[4], const uint32_t al[4],
                                          const uint32_t bh[2], const uint32_t bl[2]) {
    mma_tf32(c, ah, bh); mma_tf32(c, ah, bl); mma_tf32(c, al, bh);
}

__global__ __launch_bounds__(256) void cvt_tf32_kernel(
    const float* __restrict__ src, float* __restrict__ dst, int n4)
{
    const int i = blockIdx.x * blockDim.x + threadIdx.x;
    if (i >= n4) return;
    float4 v = ((const float4*)src)[i];
    uint4 u;
    u.x = f2tf(v.x); u.y = f2tf(v.y); u.z = f2tf(v.z); u.w = f2tf(v.w);
    ((uint4*)dst)[i] = u;
}

// ============== TF32 GEMM (NT): 3-stage cp.async, SW128-swizzled smem ==============
// C[M,N] = A[M,K] * B[N,K]^T. 128x128 tile, BK=32 (row = 32 fp32 = 128B, SW128),
// 256 threads (8 warps, warp tile 64x32), 3-stage pipeline, ONE barrier/k-tile.
#define TSTAGE_F 4096                 // floats per matrix per stage (128*32)
#define TSTAGE_B (2 * TSTAGE_F * 4)   // bytes per stage (A+B) = 32768

__global__ __launch_bounds__(256, 2) void gemm_tf32_ca_kernel(
    const float* __restrict__ A, const float* __restrict__ Bw,
    float* __restrict__ C, int M, int N, int K)
{
    extern __shared__ float sm[];

    const int tid  = threadIdx.x;
    const int lane = tid & 31;
    const int warp = tid >> 5;
    const int wm = (warp >> 2) * 64;
    const int wn = (warp & 3) * 32;
    const int bm = blockIdx.y * 128;
    const int bn = blockIdx.x * 128;

    // staging: thread -> row r (0..127), 64B half (tid&1); 4 x 16B chunks, SW128 swizzle
    const int r    = tid >> 1;
    const int ccol = (tid & 1) * 16;            // float col of first chunk
    uint32_t doff[4];
#pragma unroll
    for (int j = 0; j < 4; j++) {
        const uint32_t lc = (uint32_t)((tid & 1) * 4 + j);   // logical chunk 0..7
        doff[j] = (uint32_t)r * 128u + ((lc ^ ((uint32_t)r & 7u)) * 16u);
    }
    const float* Ag = A  + (size_t)(bm + r) * K + ccol;
    const float* Bg = Bw + (size_t)(bn + r) * K + ccol;
    const int bsz = ((bn + r) < N) ? 16 : 0;
    const uint32_t sbase = (uint32_t)__cvta_generic_to_shared(sm);

#define G_ISSUE(kt, s) do {                                                    \
        const float* ag_ = Ag + (size_t)(kt) * 32;                             \
        const float* bg_ = Bg + (size_t)(kt) * 32;                             \
        const uint32_t da_ = sbase + (uint32_t)(s) * TSTAGE_B;                 \
        const uint32_t db_ = da_ + TSTAGE_F * 4;                               \
        _Pragma("unroll")                                                      \
        for (int j_ = 0; j_ < 4; j_++)                                         \
            asm volatile("cp.async.cg.shared.global [%0], [%1], 16;"           \
                         :: "r"(da_ + doff[j_]), "l"(ag_ + j_ * 4));           \
        _Pragma("unroll")                                                      \
        for (int j_ = 0; j_ < 4; j_++)                                         \
            asm volatile("cp.async.cg.shared.global [%0], [%1], 16, %2;"       \
                         :: "r"(db_ + doff[j_]), "l"(bg_ + j_ * 4), "r"(bsz)); \
        asm volatile("cp.async.commit_group;");                                \
    } while (0)

    float acc[4][4][4];
#pragma unroll
    for (int mt = 0; mt < 4; mt++)
#pragma unroll
        for (int nt = 0; nt < 4; nt++)
#pragma unroll
            for (int i = 0; i < 4; i++) acc[mt][nt][i] = 0.f;

    const int rp = lane >> 2;          // row % 8 parity for swizzled frag loads
    const int kc = lane & 3;
    const int KT = K / 32;

    G_ISSUE(0, 0);
    G_ISSUE(1, 1);

    for (int kt = 0; kt < KT; kt++) {
        if (kt + 1 < KT) asm volatile("cp.async.wait_group 1;");
        else             asm volatile("cp.async.wait_group 0;");
        __syncthreads();
        // issue kt+2 into buffer (kt+2)%3: last read at kt-1, all warps past it
        if (kt + 2 < KT) G_ISSUE(kt + 2, (kt + 2) % 3);

        const float* As = sm + (kt % 3) * (2 * TSTAGE_F);
        const float* Bs = As + TSTAGE_F;

#pragma unroll
        for (int ks = 0; ks < 4; ks++) {
            // swizzled float index within a 32-float row for k=ks*8+kc and +4
            const int f0 = (((2 * ks)     ^ rp) << 2) + kc;
            const int f1 = (((2 * ks + 1) ^ rp) << 2) + kc;
            uint32_t af[4][4];
#pragma unroll
            for (int mt = 0; mt < 4; mt++) {
                const int m = wm + mt * 16 + rp;
                af[mt][0] = __float_as_uint(As[m       * 32 + f0]);
                af[mt][1] = __float_as_uint(As[(m + 8) * 32 + f0]);
                af[mt][2] = __float_as_uint(As[m       * 32 + f1]);
                af[mt][3] = __float_as_uint(As[(m + 8) * 32 + f1]);
            }
            uint32_t bf[4][2];
#pragma unroll
            for (int nt = 0; nt < 4; nt++) {
                const int n = wn + nt * 8 + rp;
                bf[nt][0] = __float_as_uint(Bs[n * 32 + f0]);
                bf[nt][1] = __float_as_uint(Bs[n * 32 + f1]);
            }
#pragma unroll
            for (int mt = 0; mt < 4; mt++)
#pragma unroll
                for (int nt = 0; nt < 4; nt++)
                    mma_tf32(acc[mt][nt], af[mt], bf[nt]);
        }
    }

#pragma unroll
    for (int mt = 0; mt < 4; mt++) {
        const int row = bm + wm + mt * 16 + (lane >> 2);
#pragma unroll
        for (int nt = 0; nt < 4; nt++) {
            const int col = bn + wn + nt * 8 + (lane & 3) * 2;
            if (col < N) {
                *(float2*)&C[(size_t)row * N + col]       = make_float2(acc[mt][nt][0], acc[mt][nt][1]);
                *(float2*)&C[(size_t)(row + 8) * N + col] = make_float2(acc[mt][nt][2], acc[mt][nt][3]);
            }
        }
    }
#undef G_ISSUE
}

// ============== depthwise conv + SiLU ==============
__global__ __launch_bounds__(256) void conv_silu_kernel(
    const float* __restrict__ conv_w, const float* __restrict__ conv_b)
{
    const int idx = blockIdx.x * blockDim.x + threadIdx.x;
    if (idx >= BL * CONVDIM) return;
    const int c  = idx % CONVDIM;
    const int bl = idx / CONVDIM;
    const int l  = bl & (Ll - 1);
    float acc = conv_b[c];
    const float* col = g_zx + (size_t)bl * DIP + DINNER + c;
#pragma unroll
    for (int j = 0; j < 4; j++) {
        const int ls = l - 3 + j;
        if (ls >= 0) acc = fmaf(col[(long)(j - 3) * DIP], conv_w[c * 4 + j], acc);
    }
    g_xbc[idx] = acc / (1.f + expf(-acc));
}

// ============== dt: softplus; a = dt * (-exp(A_log)) ==============
__global__ __launch_bounds__(256) void dt_kernel(
    const float* __restrict__ dt_bias, const float* __restrict__ A_log)
{
    const int idx = blockIdx.x * blockDim.x + threadIdx.x;
    if (idx >= BL * NHEADS) return;
    const int h  = idx & (NHEADS - 1);
    const int bl = idx >> 5;
    float raw = g_zx[(size_t)bl * DIP + DINNER + CONVDIM + h] + dt_bias[h];
    float dt = (raw > 20.f) ? raw : log1pf(expf(raw));
    float A = -expf(A_log[h]);
    g_dt[idx] = dt;
    g_dA[idx] = dt * A;
}

// ============== SSD K1: chunk-local Y_intra, state S_c, cumsum ca ==============
__global__ __launch_bounds__(256, 2) void ssd_chunk_kernel()
{
    extern __shared__ float smf[];
    float* sBhi = smf;
    float* sBlo = sBhi + Q * BSTR;
    float* sWhi = sBlo + Q * BSTR;   // C, later Bw
    float* sWlo = sWhi + Q * BSTR;
    float* sXhi = sWlo + Q * BSTR;   // Xt [64][XSTR]
    float* sXlo = sXhi + 64 * XSTR;
    float* sMhi = sXlo + 64 * XSTR;  // [Q][XSTR]
    float* sMlo = sMhi + Q * XSTR;
    float* s_dt = sMlo + Q * XSTR;
    float* s_ca = s_dt + Q;
    float* s_w  = s_ca + Q;

    const int tid  = threadIdx.x;
    const int lane = tid & 31;
    const int warp = tid >> 5;
    const int bx = blockIdx.x;
    const int h = bx & 31;
    const int c = (bx >> 5) & (NC - 1);
    const int b = bx >> 12;
    const int t0 = c * Q;
    const int bh = b * NHEADS + h;
    const float* xbase = g_xbc + ((size_t)b * Ll + t0) * CONVDIM;

    {
        const int t   = tid >> 3;
        const int seg = (tid & 7) * 16;
        const float4* srcB = (const float4*)(xbase + (size_t)t * CONVDIM + DINNER + seg);
        const float4* srcC = (const float4*)(xbase + (size_t)t * CONVDIM + DINNER + DSTATE + seg);
#pragma unroll
        for (int j = 0; j < 4; j++) {
            float4 vb = srcB[j], vc = srcC[j];
            const int n = seg + j * 4;
            split_store(vb.x, &sBhi[t*BSTR+n+0], &sBlo[t*BSTR+n+0]);
            split_store(vb.y, &sBhi[t*BSTR+n+1], &sBlo[t*BSTR+n+1]);
            split_store(vb.z, &sBhi[t*BSTR+n+2], &sBlo[t*BSTR+n+2]);
            split_store(vb.w, &sBhi[t*BSTR+n+3], &sBlo[t*BSTR+n+3]);
            split_store(vc.x, &sWhi[t*BSTR+n+0], &sWlo[t*BSTR+n+0]);
            split_store(vc.y, &sWhi[t*BSTR+n+1], &sWlo[t*BSTR+n+1]);
            split_store(vc.z, &sWhi[t*BSTR+n+2], &sWlo[t*BSTR+n+2]);
            split_store(vc.w, &sWhi[t*BSTR+n+3], &sWlo[t*BSTR+n+3]);
        }
        const int px = (tid & 7) * 8;
        const float4* srcX = (const float4*)(xbase + (size_t)t * CONVDIM + h * 64 + px);
#pragma unroll
        for (int j = 0; j < 2; j++) {
            float4 v = srcX[j];
            const int p = px + j * 4;
            split_store(v.x, &sXhi[(p+0)*XSTR+t], &sXlo[(p+0)*XSTR+t]);
            split_store(v.y, &sXhi[(p+1)*XSTR+t], &sXlo[(p+1)*XSTR+t]);
            split_store(v.z, &sXhi[(p+2)*XSTR+t], &sXlo[(p+2)*XSTR+t]);
            split_store(v.w, &sXhi[(p+3)*XSTR+t], &sXlo[(p+3)*XSTR+t]);
        }
    }
    if (tid < 32) {
        const size_t rb = ((size_t)b * Ll + t0 + tid) * NHEADS + h;
        const float dtv = g_dt[rb];
        float cum = g_dA[rb];
        s_dt[tid] = dtv;
#pragma unroll
        for (int o = 1; o < 32; o <<= 1) {
            float nb = __shfl_up_sync(0xffffffffu, cum, o);
            if (tid >= o) cum += nb;
        }
        s_ca[tid] = cum;
        g_ca[((size_t)bh * NC + c) * Q + tid] = cum;
        const float tot = __shfl_sync(0xffffffffu, cum, 31);
        s_w[tid] = dtv * expf(tot - cum);
    }
    __syncthreads();

    const int wmG = (warp >> 2) * 16;
    const int wnG = (warp & 3) * 8;
    float gacc[4] = {0.f, 0.f, 0.f, 0.f};
#pragma unroll
    for (int ks = 0; ks < 16; ks++) {
        const int k = ks * 8 + (lane & 3);
        const int m = wmG + (lane >> 2);
        uint32_t ah[4], al[4];
        ah[0] = __float_as_uint(sWhi[m*BSTR+k]);     al[0] = __float_as_uint(sWlo[m*BSTR+k]);
        ah[1] = __float_as_uint(sWhi[(m+8)*BSTR+k]); al[1] = __float_as_uint(sWlo[(m+8)*BSTR+k]);
        ah[2] = __float_as_uint(sWhi[m*BSTR+k+4]);   al[2] = __float_as_uint(sWlo[m*BSTR+k+4]);
        ah[3] = __float_as_uint(sWhi[(m+8)*BSTR+k+4]);al[3] = __float_as_uint(sWlo[(m+8)*BSTR+k+4]);
        const int n = wnG + (lane >> 2);
        uint32_t bh2[2], bl2[2];
        bh2[0] = __float_as_uint(sBhi[n*BSTR+k]);    bl2[0] = __float_as_uint(sBlo[n*BSTR+k]);
        bh2[1] = __float_as_uint(sBhi[n*BSTR+k+4]);  bl2[1] = __float_as_uint(sBlo[n*BSTR+k+4]);
        mma_split(gacc, ah, al, bh2, bl2);
    }
    __syncthreads();

    {
#pragma unroll
        for (int i = 0; i < 4; i++) {
            const int t = wmG + (lane >> 2) + (i >> 1) * 8;
            const int s = wnG + (lane & 3) * 2 + (i & 1);
            float v = 0.f;
            if (s <= t) v = gacc[i] * s_dt[s] * expf(s_ca[t] - s_ca[s]);
            split_store(v, &sMhi[t*XSTR+s], &sMlo[t*XSTR+s]);
        }
        const int tB = tid >> 3;
        const int n0 = (tid & 7) * 16;
        const float w = s_w[tB];
#pragma unroll
        for (int i = 0; i < 16; i++) {
            const int n = n0 + i;
            float v = (sBhi[tB*BSTR+n] + sBlo[tB*BSTR+n]) * w;
            split_store(v, &sWhi[tB*BSTR+n], &sWlo[tB*BSTR+n]);
        }
    }
    __syncthreads();

    {
        const int wm = (warp >> 2) * 16;
        const int wp = (warp & 3) * 16;
        float yacc[2][4];
#pragma unroll
        for (int nt = 0; nt < 2; nt++)
#pragma unroll
            for (int i = 0; i < 4; i++) yacc[nt][i] = 0.f;
#pragma unroll
        for (int ks = 0; ks < 4; ks++) {
            const int k = ks * 8 + (lane & 3);
            const int m = wm + (lane >> 2);
            uint32_t ah[4], al[4];
            ah[0] = __float_as_uint(sMhi[m*XSTR+k]);      al[0] = __float_as_uint(sMlo[m*XSTR+k]);
            ah[1] = __float_as_uint(sMhi[(m+8)*XSTR+k]);  al[1] = __float_as_uint(sMlo[(m+8)*XSTR+k]);
            ah[2] = __float_as_uint(sMhi[m*XSTR+k+4]);    al[2] = __float_as_uint(sMlo[m*XSTR+k+4]);
            ah[3] = __float_as_uint(sMhi[(m+8)*XSTR+k+4]);al[3] = __float_as_uint(sMlo[(m+8)*XSTR+k+4]);
#pragma unroll
            for (int nt = 0; nt < 2; nt++) {
                const int p = wp + nt * 8 + (lane >> 2);
                uint32_t bh2[2], bl2[2];
                bh2[0] = __float_as_uint(sXhi[p*XSTR+k]);   bl2[0] = __float_as_uint(sXlo[p*XSTR+k]);
                bh2[1] = __float_as_uint(sXhi[p*XSTR+k+4]); bl2[1] = __float_as_uint(sXlo[p*XSTR+k+4]);
                mma_split(yacc[nt], ah, al, bh2, bl2);
            }
        }
        float* yout = g_y + ((size_t)b * Ll + t0) * DINNER + h * 64;
#pragma unroll
        for (int nt = 0; nt < 2; nt++) {
            const int t = wm + (lane >> 2);
            const int p = wp + nt * 8 + (lane & 3) * 2;
            *(float2*)&yout[(size_t)t * DINNER + p]       = make_float2(yacc[nt][0], yacc[nt][1]);
            *(float2*)&yout[(size_t)(t + 8) * DINNER + p] = make_float2(yacc[nt][2], yacc[nt][3]);
        }
    }

    {
        const int wp = (warp >> 1) * 16;
        const int wn = (warp & 1) * 64;
        float sacc[8][4];
#pragma unroll
        for (int nt = 0; nt < 8; nt++)
#pragma unroll
            for (int i = 0; i < 4; i++) sacc[nt][i] = 0.f;
#pragma unroll
        for (int ks = 0; ks < 4; ks++) {
            const int k = ks * 8 + (lane & 3);
            const int m = wp + (lane >> 2);
            uint32_t ah[4], al[4];
            ah[0] = __float_as_uint(sXhi[m*XSTR+k]);      al[0] = __float_as_uint(sXlo[m*XSTR+k]);
            ah[1] = __float_as_uint(sXhi[(m+8)*XSTR+k]);  al[1] = __float_as_uint(sXlo[(m+8)*XSTR+k]);
            ah[2] = __float_as_uint(sXhi[m*XSTR+k+4]);    al[2] = __float_as_uint(sXlo[m*XSTR+k+4]);
            ah[3] = __float_as_uint(sXhi[(m+8)*XSTR+k+4]);al[3] = __float_as_uint(sXlo[(m+8)*XSTR+k+4]);
#pragma unroll
            for (int nt = 0; nt < 8; nt++) {
                const int n = wn + nt * 8 + (lane >> 2);
                uint32_t bh2[2], bl2[2];
                bh2[0] = __float_as_uint(sWhi[k*BSTR+n]);     bl2[0] = __float_as_uint(sWlo[k*BSTR+n]);
                bh2[1] = __float_as_uint(sWhi[(k+4)*BSTR+n]); bl2[1] = __float_as_uint(sWlo[(k+4)*BSTR+n]);
                mma_split(sacc[nt], ah, al, bh2, bl2);
            }
        }
        float* sout = g_state + ((size_t)bh * NC + c) * SSTATE;
#pragma unroll
        for (int nt = 0; nt < 8; nt++) {
            const int p = wp + (lane >> 2);
            const int n = wn + nt * 8 + (lane & 3) * 2;
            *(float2*)&sout[(size_t)p * DSTATE + n]       = make_float2(sacc[nt][0], sacc[nt][1]);
            *(float2*)&sout[(size_t)(p + 8) * DSTATE + n] = make_float2(sacc[nt][2], sacc[nt][3]);
        }
    }
}

// ============== SSD K2: inter-chunk exclusive state scan ==============
__global__ __launch_bounds__(256) void ssd_state_scan_kernel()
{
    const int bh = blockIdx.x >> 4;
    const int sl = blockIdx.x & 15;
    const int off = sl * 512 + threadIdx.x * 2;
    const size_t base = (size_t)bh * NC * SSTATE + off;
    const float* ca = g_ca + (size_t)bh * NC * Q + (Q - 1);

    float2 run = make_float2(0.f, 0.f);
#pragma unroll 4
    for (int c = 0; c < NC; c++) {
        *(float2*)&g_sprev[base + (size_t)c * SSTATE] = run;
        const float P = expf(ca[(size_t)c * Q]);
        const float2 v = *(const float2*)&g_state[base + (size_t)c * SSTATE];
        run.x = fmaf(run.x, P, v.x);
        run.y = fmaf(run.y, P, v.y);
    }
}

// ============== SSD K3: y += exp(ca)*C@S_prev^T + D*x ==============
__global__ __launch_bounds__(256, 2) void ssd_inter_kernel(const float* __restrict__ Dp)
{
    extern __shared__ float smf[];
    float* sChi = smf;
    float* sClo = sChi + Q * BSTR;
    float* sShi = sClo + Q * BSTR;
    float* sSlo = sShi + 64 * BSTR;
    float* s_ca = sSlo + 64 * BSTR;

    const int tid  = threadIdx.x;
    const int lane = tid & 31;
    const int warp = tid >> 5;
    const int bx = blockIdx.x;
    const int h = bx & 31;
    const int c = (bx >> 5) & (NC - 1);
    const int b = bx >> 12;
    const int t0 = c * Q;
    const int bh = b * NHEADS + h;
    const float* xbase = g_xbc + ((size_t)b * Ll + t0) * CONVDIM;

    {
        const int t   = tid >> 3;
        const int seg = (tid & 7) * 16;
        const float4* srcC = (const float4*)(xbase + (size_t)t * CONVDIM + DINNER + DSTATE + seg);
#pragma unroll
        for (int j = 0; j < 4; j++) {
            float4 v = srcC[j];
            const int n = seg + j * 4;
            split_store(v.x, &sChi[t*BSTR+n+0], &sClo[t*BSTR+n+0]);
            split_store(v.y, &sChi[t*BSTR+n+1], &sClo[t*BSTR+n+1]);
            split_store(v.z, &sChi[t*BSTR+n+2], &sClo[t*BSTR+n+2]);
            split_store(v.w, &sChi[t*BSTR+n+3], &sClo[t*BSTR+n+3]);
        }
        const int p   = tid >> 2;
        const int nsg = (tid & 3) * 32;
        const float4* srcS = (const float4*)(g_sprev + ((size_t)bh * NC + c) * SSTATE
                                             + (size_t)p * DSTATE + nsg);
#pragma unroll
        for (int j = 0; j < 8; j++) {
            float4 v = srcS[j];
            const int n = nsg + j * 4;
            split_store(v.x, &sShi[p*BSTR+n+0], &sSlo[p*BSTR+n+0]);
            split_store(v.y, &sShi[p*BSTR+n+1], &sSlo[p*BSTR+n+1]);
            split_store(v.z, &sShi[p*BSTR+n+2], &sSlo[p*BSTR+n+2]);
            split_store(v.w, &sShi[p*BSTR+n+3], &sSlo[p*BSTR+n+3]);
        }
        if (tid < 32) s_ca[tid] = g_ca[((size_t)bh * NC + c) * Q + tid];
    }
    __syncthreads();

    const int wm = (warp >> 2) * 16;
    const int wp = (warp & 3) * 16;
    float acc[2][4];
#pragma unroll
    for (int nt = 0; nt < 2; nt++)
#pragma unroll
        for (int i = 0; i < 4; i++) acc[nt][i] = 0.f;

#pragma unroll
    for (int ks = 0; ks < 16; ks++) {
        const int k = ks * 8 + (lane & 3);
        const int m = wm + (lane >> 2);
        uint32_t ah[4], al[4];
        ah[0] = __float_as_uint(sChi[m*BSTR+k]);      al[0] = __float_as_uint(sClo[m*BSTR+k]);
        ah[1] = __float_as_uint(sChi[(m+8)*BSTR+k]);  al[1] = __float_as_uint(sClo[(m+8)*BSTR+k]);
        ah[2] = __float_as_uint(sChi[m*BSTR+k+4]);    al[2] = __float_as_uint(sClo[m*BSTR+k+4]);
        ah[3] = __float_as_uint(sChi[(m+8)*BSTR+k+4]);al[3] = __float_as_uint(sClo[(m+8)*BSTR+k+4]);
#pragma unroll
        for (int nt = 0; nt < 2; nt++) {
            const int p = wp + nt * 8 + (lane >> 2);
            uint32_t bh2[2], bl2[2];
            bh2[0] = __float_as_uint(sShi[p*BSTR+k]);   bl2[0] = __float_as_uint(sSlo[p*BSTR+k]);
            bh2[1] = __float_as_uint(sShi[p*BSTR+k+4]); bl2[1] = __float_as_uint(sSlo[p*BSTR+k+4]);
            mma_split(acc[nt], ah, al, bh2, bl2);
        }
    }

    const float Dh = Dp[h];
    float* yout = g_y + ((size_t)b * Ll + t0) * DINNER + h * 64;
    const float* xsrc = xbase + h * 64;
#pragma unroll
    for (int nt = 0; nt < 2; nt++) {
#pragma unroll
        for (int half = 0; half < 2; half++) {
            const int t = wm + (lane >> 2) + half * 8;
            const int p = wp + nt * 8 + (lane & 3) * 2;
            const float e = expf(s_ca[t]);
            float2 xv = *(const float2*)(xsrc + (size_t)t * CONVDIM + p);
            float2 yo = *(float2*)(yout + (size_t)t * DINNER + p);
            yo.x += e * acc[nt][half * 2 + 0] + Dh * xv.x;
            yo.y += e * acc[nt][half * 2 + 1] + Dh * xv.y;
            *(float2*)(yout + (size_t)t * DINNER + p) = yo;
        }
    }
}

// ============== gate + RMSnorm (tf32-rounded out) ==============
__global__ __launch_bounds__(256) void gatenorm_kernel(const float* __restrict__ norm_w)
{
    const int row = blockIdx.x;
    const float* zrow = g_zx + (size_t)row * DIP;
    float* yrow = g_y + (size_t)row * DINNER;

    float v[8];
    float ss = 0.f;
#pragma unroll
    for (int i = 0; i < 8; i++) {
        const int c = threadIdx.x + i * 256;
        float d = yrow[c];
        float z = zrow[c];
        float g = d * (z / (1.f + expf(-z)));
        v[i] = g;
        ss = fmaf(g, g, ss);
    }
#pragma unroll
    for (int o = 16; o; o >>= 1) ss += __shfl_xor_sync(0xffffffffu, ss, o);

    __shared__ float red[8];
    if ((threadIdx.x & 31) == 0) red[threadIdx.x >> 5] = ss;
    __syncthreads();
    float tot = 0.f;
#pragma unroll
    for (int w = 0; w < 8; w++) tot += red[w];
    const float scale = rsqrtf(tot * (1.f / (float)DINNER) + 1e-5f);

#pragma unroll
    for (int i = 0; i < 8; i++) {
        const int c = threadIdx.x + i * 256;
        yrow[c] = __uint_as_float(f2tf(v[i] * scale * norm_w[c]));
    }
}

// ============== launch ==============
extern "C" void kernel_launch(void* const* d_in, const int* in_sizes, int n_in,
                              void* d_out, int out_size)
{
    const float* x          = (const float*)d_in[0];
    const float* in_proj_w  = (const float*)d_in[1];
    const float* conv_w     = (const float*)d_in[2];
    const float* conv_b     = (const float*)d_in[3];
    const float* dt_bias    = (const float*)d_in[4];
    const float* A_log      = (const float*)d_in[5];
    const float* Dp         = (const float*)d_in[6];
    const float* norm_w     = (const float*)d_in[7];
    const float* out_proj_w = (const float*)d_in[8];
    float* out = (float*)d_out;

    float *zx, *yb, *xc, *w1, *w2;
    cudaGetSymbolAddress((void**)&zx, g_zx);
    cudaGetSymbolAddress((void**)&yb, g_y);
    cudaGetSymbolAddress((void**)&xc, g_xc);
    cudaGetSymbolAddress((void**)&w1, g_w1);
    cudaGetSymbolAddress((void**)&w2, g_w2);

    const int gemm_smem = 3 * TSTAGE_B;   // 98304
    const int k1_smem = (4 * Q * BSTR + 2 * 64 * XSTR + 2 * Q * XSTR + 3 * Q) * 4;
    const int k3_smem = (2 * Q * BSTR + 2 * 64 * BSTR + Q) * 4;
    cudaFuncSetAttribute(gemm_tf32_ca_kernel,
                         cudaFuncAttributeMaxDynamicSharedMemorySize, gemm_smem);
    cudaFuncSetAttribute(ssd_chunk_kernel,
                         cudaFuncAttributeMaxDynamicSharedMemorySize, k1_smem);
    cudaFuncSetAttribute(ssd_inter_kernel,
                         cudaFuncAttributeMaxDynamicSharedMemorySize, k3_smem);

    {
        int n4;
        n4 = (BL * DMODEL) / 4;
        cvt_tf32_kernel<<<(n4 + 255) / 256, 256>>>(x, xc, n4);
        n4 = (DIP * DMODEL) / 4;
        cvt_tf32_kernel<<<(n4 + 255) / 256, 256>>>(in_proj_w, w1, n4);
        n4 = (DOUT * DINNER) / 4;
        cvt_tf32_kernel<<<(n4 + 255) / 256, 256>>>(out_proj_w, w2, n4);
    }
    {
        dim3 grid((DIP + 127) / 128, BL / 128);
        gemm_tf32_ca_kernel<<<grid, 256, gemm_smem>>>(xc, w1, zx, BL, DIP, DMODEL);
    }
    {
        const int total = BL * CONVDIM;
        conv_silu_kernel<<<(total + 255) / 256, 256>>>(conv_w, conv_b);
    }
    dt_kernel<<<(BL * NHEADS) / 256, 256>>>(dt_bias, A_log);
    ssd_chunk_kernel<<<Bb * NC * NHEADS, 256, k1_smem>>>();
    ssd_state_scan_kernel<<<Bb * NHEADS * 16, 256>>>();
    ssd_inter_kernel<<<Bb * NC * NHEADS, 256, k3_smem>>>(Dp);
    gatenorm_kernel<<<BL, 256>>>(norm_w);
    {
        dim3 grid(DOUT / 128, BL / 128);
        gemm_tf32_ca_kernel<<<grid, 256, gemm_smem>>>(yb, w2, out, BL, DOUT, DINNER);
    }
}